// round 3
// baseline (speedup 1.0000x reference)
#include <cuda_runtime.h>
#include <math.h>

#define NMAX 100000
#define EMAX 1600000
#define DF   128
#define NG   128
#define NP   64
#define NC   10

// ---------------- scratch (static device globals; no allocs allowed) --------
__device__ __align__(16) int   g_deg_out[NMAX];
__device__ __align__(16) int   g_deg_in[NMAX];
__device__ __align__(16) float g_norm_out[NMAX];
__device__ __align__(16) float g_norm_in[NMAX];
__device__ __align__(16) int   g_off[NMAX + 1];
__device__ __align__(16) int   g_cursor[NMAX];
__device__ __align__(16) int   g_csr_src[EMAX];
__device__ __align__(16) float g_bufA[(size_t)NMAX * DF];
__device__ __align__(16) float g_bufB[(size_t)NMAX * DF];
__device__ __align__(16) float g_hg[NG * DF];
__device__ __align__(16) float g_cnt[NG];
__device__ __align__(16) int   g_bsum[128];

// ---------------- init ------------------------------------------------------
__global__ void k_zero(int n) {
    int i = blockIdx.x * blockDim.x + threadIdx.x;
    int stride = gridDim.x * blockDim.x;
    for (int j = i; j < n; j += stride) { g_deg_out[j] = 0; g_deg_in[j] = 0; }
    for (int j = i; j < NG * DF; j += stride) g_hg[j] = 0.0f;
    for (int j = i; j < NG; j += stride) g_cnt[j] = 0.0f;
}

__global__ void k_deg(const int* __restrict__ src,
                      const int* __restrict__ dst, int e) {
    int i = blockIdx.x * blockDim.x + threadIdx.x;
    if (i < e) {
        atomicAdd(&g_deg_out[src[i]], 1);
        atomicAdd(&g_deg_in[dst[i]], 1);
    }
}

__global__ void k_norms(int n) {
    int i = blockIdx.x * blockDim.x + threadIdx.x;
    if (i < n) {
        g_norm_out[i] = rsqrtf(fmaxf((float)g_deg_out[i], 1.0f));
        g_norm_in[i]  = rsqrtf(fmaxf((float)g_deg_in[i],  1.0f));
    }
}

// ---------------- prefix sum of in-degrees -> CSR offsets -------------------
__global__ void k_scan1(int n) {
    __shared__ int sh[1024];
    int t = threadIdx.x;
    int idx = blockIdx.x * 1024 + t;
    sh[t] = (idx < n) ? g_deg_in[idx] : 0;
    __syncthreads();
    for (int s = 512; s > 0; s >>= 1) {
        if (t < s) sh[t] += sh[t + s];
        __syncthreads();
    }
    if (t == 0) g_bsum[blockIdx.x] = sh[0];
}

__global__ void k_scan2(int nb) {
    if (threadIdx.x == 0 && blockIdx.x == 0) {
        int run = 0;
        for (int i = 0; i < nb; i++) { int v = g_bsum[i]; g_bsum[i] = run; run += v; }
    }
}

__global__ void k_scan3(int n, int e) {
    __shared__ int sh[1024];
    int t = threadIdx.x;
    int idx = blockIdx.x * 1024 + t;
    int v = (idx < n) ? g_deg_in[idx] : 0;
    sh[t] = v;
    __syncthreads();
    for (int s = 1; s < 1024; s <<= 1) {
        int x = (t >= s) ? sh[t - s] : 0;
        __syncthreads();
        sh[t] += x;
        __syncthreads();
    }
    int excl = sh[t] - v;
    if (idx < n) {
        int o = g_bsum[blockIdx.x] + excl;
        g_off[idx] = o;
        g_cursor[idx] = o;
    }
    if (blockIdx.x == 0 && t == 0) g_off[n] = e;
}

__global__ void k_fill(const int* __restrict__ src,
                       const int* __restrict__ dst, int e) {
    int i = blockIdx.x * blockDim.x + threadIdx.x;
    if (i < e) {
        int d = dst[i];
        int p = atomicAdd(&g_cursor[d], 1);
        g_csr_src[p] = src[i];
    }
}

// ---------------- aggregation: one warp per dst node ------------------------
// out[d] = in_norm[d] * sum_{e in csr(d)} out_norm[src_e] * x[src_e]
__global__ void k_agg(const float* __restrict__ x, float* __restrict__ out, int n) {
    int w = (blockIdx.x * blockDim.x + threadIdx.x) >> 5;
    int lane = threadIdx.x & 31;
    if (w >= n) return;
    int beg = g_off[w], end = g_off[w + 1];
    const float4* __restrict__ x4 = (const float4*)x;
    float ax = 0.f, ay = 0.f, az = 0.f, aw = 0.f;
    int e = beg;
    for (; e + 1 < end; e += 2) {
        int s0 = g_csr_src[e];
        int s1 = g_csr_src[e + 1];
        float w0 = g_norm_out[s0];
        float w1 = g_norm_out[s1];
        float4 v0 = x4[(size_t)s0 * 32 + lane];
        float4 v1 = x4[(size_t)s1 * 32 + lane];
        ax += w0 * v0.x; ay += w0 * v0.y; az += w0 * v0.z; aw += w0 * v0.w;
        ax += w1 * v1.x; ay += w1 * v1.y; az += w1 * v1.z; aw += w1 * v1.w;
    }
    if (e < end) {
        int s0 = g_csr_src[e];
        float w0 = g_norm_out[s0];
        float4 v0 = x4[(size_t)s0 * 32 + lane];
        ax += w0 * v0.x; ay += w0 * v0.y; az += w0 * v0.z; aw += w0 * v0.w;
    }
    float wi = g_norm_in[w];
    float4 r; r.x = ax * wi; r.y = ay * wi; r.z = az * wi; r.w = aw * wi;
    ((float4*)out)[(size_t)w * 32 + lane] = r;
}

// ---------------- GEMM: C[n,128] = A[n,128] @ W[128,128] + b, optional relu -
// block: 128 rows x 128 cols; 256 threads; each thread 8x8 register tile.
__global__ __launch_bounds__(256) void k_gemm(const float* __restrict__ A,
                                              const float* __restrict__ W,
                                              const float* __restrict__ bias,
                                              float* __restrict__ Cout,
                                              int n, int relu) {
    __shared__ float sW[16 * 128];        // W tile, k-major
    __shared__ float sA[128][17];         // A tile, row-major padded
    int tid = threadIdx.x;
    int tx = tid & 15;                    // col group: cols tx*8 .. tx*8+7
    int ty = tid >> 4;                    // row group: rows ty*8 .. ty*8+7
    int rowBase = blockIdx.x * 128;

    float acc[8][8];
#pragma unroll
    for (int r = 0; r < 8; r++)
#pragma unroll
        for (int c = 0; c < 8; c++) acc[r][c] = 0.0f;

    for (int k0 = 0; k0 < 128; k0 += 16) {
        __syncthreads();
        // load W tile: 16x128 = 512 float4
#pragma unroll
        for (int i = tid; i < 512; i += 256) {
            ((float4*)sW)[i] = ((const float4*)(W + (size_t)k0 * 128))[i];
        }
        // load A tile: 128 rows x 16 cols = 512 float4
#pragma unroll
        for (int i = tid; i < 512; i += 256) {
            int r = i >> 2, c4 = i & 3;
            int gr = rowBase + r;
            float4 v = make_float4(0.f, 0.f, 0.f, 0.f);
            if (gr < n) v = *(const float4*)&A[(size_t)gr * 128 + k0 + c4 * 4];
            sA[r][c4 * 4 + 0] = v.x;
            sA[r][c4 * 4 + 1] = v.y;
            sA[r][c4 * 4 + 2] = v.z;
            sA[r][c4 * 4 + 3] = v.w;
        }
        __syncthreads();
#pragma unroll
        for (int kk = 0; kk < 16; kk++) {
            float a[8];
#pragma unroll
            for (int r = 0; r < 8; r++) a[r] = sA[ty * 8 + r][kk];
            float4 b0 = *(float4*)&sW[kk * 128 + tx * 8];
            float4 b1 = *(float4*)&sW[kk * 128 + tx * 8 + 4];
            float bb[8] = {b0.x, b0.y, b0.z, b0.w, b1.x, b1.y, b1.z, b1.w};
#pragma unroll
            for (int r = 0; r < 8; r++)
#pragma unroll
                for (int c = 0; c < 8; c++) acc[r][c] += a[r] * bb[c];
        }
    }

    float4 bv0 = *(const float4*)&bias[tx * 8];
    float4 bv1 = *(const float4*)&bias[tx * 8 + 4];
    float bb[8] = {bv0.x, bv0.y, bv0.z, bv0.w, bv1.x, bv1.y, bv1.z, bv1.w};
#pragma unroll
    for (int r = 0; r < 8; r++) {
        int gr = rowBase + ty * 8 + r;
        if (gr < n) {
            float4 o0, o1;
            float v0 = acc[r][0] + bb[0], v1 = acc[r][1] + bb[1];
            float v2 = acc[r][2] + bb[2], v3 = acc[r][3] + bb[3];
            float v4 = acc[r][4] + bb[4], v5 = acc[r][5] + bb[5];
            float v6 = acc[r][6] + bb[6], v7 = acc[r][7] + bb[7];
            if (relu) {
                v0 = fmaxf(v0, 0.f); v1 = fmaxf(v1, 0.f); v2 = fmaxf(v2, 0.f); v3 = fmaxf(v3, 0.f);
                v4 = fmaxf(v4, 0.f); v5 = fmaxf(v5, 0.f); v6 = fmaxf(v6, 0.f); v7 = fmaxf(v7, 0.f);
            }
            o0.x = v0; o0.y = v1; o0.z = v2; o0.w = v3;
            o1.x = v4; o1.y = v5; o1.z = v6; o1.w = v7;
            *(float4*)&Cout[(size_t)gr * 128 + tx * 8] = o0;
            *(float4*)&Cout[(size_t)gr * 128 + tx * 8 + 4] = o1;
        }
    }
}

// ---------------- per-graph mean pooling (graph_ids sorted) -----------------
#define NPB 256
__global__ void k_pool(const float* __restrict__ x,
                       const int* __restrict__ gids, int n) {
    int f = threadIdx.x;          // feature 0..127
    int start = blockIdx.x * NPB;
    int end = min(start + NPB, n);
    if (start >= n) return;
    float sum = 0.0f;
    int cur = gids[start];
    int cnt = 0;
    for (int nd = start; nd < end; nd++) {
        int gid = gids[nd];
        if (gid != cur) {
            atomicAdd(&g_hg[cur * DF + f], sum);
            if (f == 0) atomicAdd(&g_cnt[cur], (float)cnt);
            sum = 0.0f; cnt = 0; cur = gid;
        }
        sum += x[(size_t)nd * DF + f];
        cnt++;
    }
    atomicAdd(&g_hg[cur * DF + f], sum);
    if (f == 0) atomicAdd(&g_cnt[cur], (float)cnt);
}

// ---------------- final classifier: [G, 128+64] @ Wc + bc -------------------
__global__ void k_final(const float* __restrict__ perm,
                        const float* __restrict__ Wc,
                        const float* __restrict__ bc,
                        float* __restrict__ out) {
    int g = blockIdx.x;
    int c = threadIdx.x;
    if (c >= NC) return;
    float inv = 1.0f / fmaxf(g_cnt[g], 1.0f);
    float acc = bc[c];
#pragma unroll 4
    for (int j = 0; j < DF; j++)
        acc += g_hg[g * DF + j] * inv * Wc[j * NC + c];
#pragma unroll 4
    for (int j = 0; j < NP; j++)
        acc += perm[g * NP + j] * Wc[(DF + j) * NC + c];
    out[g * NC + c] = acc;
}

// ---------------- launch ----------------------------------------------------
extern "C" void kernel_launch(void* const* d_in, const int* in_sizes, int n_in,
                              void* d_out, int out_size) {
    const float* h    = (const float*)d_in[0];
    const float* perm = (const float*)d_in[1];
    const float* W1   = (const float*)d_in[2];
    const float* b1   = (const float*)d_in[3];
    const float* W2   = (const float*)d_in[4];
    const float* b2   = (const float*)d_in[5];
    const float* Wc   = (const float*)d_in[6];
    const float* bc   = (const float*)d_in[7];
    const int* src  = (const int*)d_in[8];
    const int* dst  = (const int*)d_in[9];
    const int* gids = (const int*)d_in[10];

    int n = in_sizes[0] / DF;   // 100000
    int e = in_sizes[8];        // 1600000
    float* out = (float*)d_out;

    float *bufA, *bufB;
    cudaGetSymbolAddress((void**)&bufA, g_bufA);
    cudaGetSymbolAddress((void**)&bufB, g_bufB);

    int nb = (n + 1023) / 1024;

    k_zero<<<256, 256>>>(n);
    k_deg<<<(e + 255) / 256, 256>>>(src, dst, e);
    k_norms<<<(n + 255) / 256, 256>>>(n);
    k_scan1<<<nb, 1024>>>(n);
    k_scan2<<<1, 32>>>(nb);
    k_scan3<<<nb, 1024>>>(n, e);
    k_fill<<<(e + 255) / 256, 256>>>(src, dst, e);

    // layer 1: agg(h) -> bufA ; gemm(bufA, W1) + relu -> bufB
    k_agg<<<(n * 32 + 255) / 256, 256>>>(h, bufA, n);
    k_gemm<<<(n + 127) / 128, 256>>>(bufA, W1, b1, bufB, n, 1);

    // layer 2: agg(bufB) -> bufA ; gemm(bufA, W2) -> bufB
    k_agg<<<(n * 32 + 255) / 256, 256>>>(bufB, bufA, n);
    k_gemm<<<(n + 127) / 128, 256>>>(bufA, W2, b2, bufB, n, 0);

    // pooling + classifier
    k_pool<<<(n + NPB - 1) / NPB, 128>>>(bufB, gids, n);
    k_final<<<NG, 32>>>(perm, Wc, bc, out);
}

// round 4
// speedup vs baseline: 1.2253x; 1.2253x over previous
#include <cuda_runtime.h>
#include <math.h>
#include <stdint.h>

#define NMAX 100000
#define EMAX 1600000
#define DF   128
#define NG   128
#define NP   64
#define NC   10

// ---------------- scratch (static device globals; no allocs allowed) --------
__device__ __align__(16) int   g_deg_out[NMAX];
__device__ __align__(16) int   g_deg_in[NMAX];
__device__ __align__(16) float g_norm_out[NMAX];
__device__ __align__(16) float g_norm_in[NMAX];
__device__ __align__(16) int   g_off[NMAX + 1];
__device__ __align__(16) int   g_cursor[NMAX];
__device__ __align__(16) int   g_csr_src[EMAX];
__device__ __align__(16) float g_bufA[(size_t)NMAX * DF];
__device__ __align__(16) float g_bufB[(size_t)NMAX * DF];
__device__ __align__(16) float g_hg[NG * DF];
__device__ __align__(16) float g_cnt[NG];
__device__ __align__(16) int   g_bsum[128];

// ---------------- init ------------------------------------------------------
__global__ void k_zero(int n) {
    int i = blockIdx.x * blockDim.x + threadIdx.x;
    int stride = gridDim.x * blockDim.x;
    for (int j = i; j < n; j += stride) { g_deg_out[j] = 0; g_deg_in[j] = 0; }
    for (int j = i; j < NG * DF; j += stride) g_hg[j] = 0.0f;
    for (int j = i; j < NG; j += stride) g_cnt[j] = 0.0f;
}

__global__ void k_deg(const int* __restrict__ src,
                      const int* __restrict__ dst, int e) {
    int i = blockIdx.x * blockDim.x + threadIdx.x;
    if (i < e) {
        atomicAdd(&g_deg_out[src[i]], 1);
        atomicAdd(&g_deg_in[dst[i]], 1);
    }
}

__global__ void k_norms(int n) {
    int i = blockIdx.x * blockDim.x + threadIdx.x;
    if (i < n) {
        g_norm_out[i] = rsqrtf(fmaxf((float)g_deg_out[i], 1.0f));
        g_norm_in[i]  = rsqrtf(fmaxf((float)g_deg_in[i],  1.0f));
    }
}

// ---------------- prefix sum of in-degrees -> CSR offsets -------------------
__global__ void k_scan1(int n) {
    __shared__ int sh[1024];
    int t = threadIdx.x;
    int idx = blockIdx.x * 1024 + t;
    sh[t] = (idx < n) ? g_deg_in[idx] : 0;
    __syncthreads();
    for (int s = 512; s > 0; s >>= 1) {
        if (t < s) sh[t] += sh[t + s];
        __syncthreads();
    }
    if (t == 0) g_bsum[blockIdx.x] = sh[0];
}

__global__ void k_scan2(int nb) {
    if (threadIdx.x == 0 && blockIdx.x == 0) {
        int run = 0;
        for (int i = 0; i < nb; i++) { int v = g_bsum[i]; g_bsum[i] = run; run += v; }
    }
}

__global__ void k_scan3(int n, int e) {
    __shared__ int sh[1024];
    int t = threadIdx.x;
    int idx = blockIdx.x * 1024 + t;
    int v = (idx < n) ? g_deg_in[idx] : 0;
    sh[t] = v;
    __syncthreads();
    for (int s = 1; s < 1024; s <<= 1) {
        int x = (t >= s) ? sh[t - s] : 0;
        __syncthreads();
        sh[t] += x;
        __syncthreads();
    }
    int excl = sh[t] - v;
    if (idx < n) {
        int o = g_bsum[blockIdx.x] + excl;
        g_off[idx] = o;
        g_cursor[idx] = o;
    }
    if (blockIdx.x == 0 && t == 0) g_off[n] = e;
}

__global__ void k_fill(const int* __restrict__ src,
                       const int* __restrict__ dst, int e) {
    int i = blockIdx.x * blockDim.x + threadIdx.x;
    if (i < e) {
        int d = dst[i];
        int p = atomicAdd(&g_cursor[d], 1);
        g_csr_src[p] = src[i];
    }
}

// ---------------- aggregation: one warp per dst node ------------------------
// out[d] = in_norm[d] * sum_{e} (useNorm ? out_norm[src]*x[src] : x[src])
template <int USE_NORM>
__global__ void k_agg(const float* __restrict__ x, float* __restrict__ out, int n) {
    int w = (blockIdx.x * blockDim.x + threadIdx.x) >> 5;
    int lane = threadIdx.x & 31;
    if (w >= n) return;
    int beg = g_off[w], end = g_off[w + 1];
    const float4* __restrict__ x4 = (const float4*)x;
    float ax = 0.f, ay = 0.f, az = 0.f, aw = 0.f;
    int e = beg;
    for (; e + 3 < end; e += 4) {
        int s0 = g_csr_src[e];
        int s1 = g_csr_src[e + 1];
        int s2 = g_csr_src[e + 2];
        int s3 = g_csr_src[e + 3];
        float w0 = USE_NORM ? g_norm_out[s0] : 1.0f;
        float w1 = USE_NORM ? g_norm_out[s1] : 1.0f;
        float w2 = USE_NORM ? g_norm_out[s2] : 1.0f;
        float w3 = USE_NORM ? g_norm_out[s3] : 1.0f;
        float4 v0 = x4[(size_t)s0 * 32 + lane];
        float4 v1 = x4[(size_t)s1 * 32 + lane];
        float4 v2 = x4[(size_t)s2 * 32 + lane];
        float4 v3 = x4[(size_t)s3 * 32 + lane];
        ax += w0 * v0.x; ay += w0 * v0.y; az += w0 * v0.z; aw += w0 * v0.w;
        ax += w1 * v1.x; ay += w1 * v1.y; az += w1 * v1.z; aw += w1 * v1.w;
        ax += w2 * v2.x; ay += w2 * v2.y; az += w2 * v2.z; aw += w2 * v2.w;
        ax += w3 * v3.x; ay += w3 * v3.y; az += w3 * v3.z; aw += w3 * v3.w;
    }
    for (; e < end; e++) {
        int s0 = g_csr_src[e];
        float w0 = USE_NORM ? g_norm_out[s0] : 1.0f;
        float4 v0 = x4[(size_t)s0 * 32 + lane];
        ax += w0 * v0.x; ay += w0 * v0.y; az += w0 * v0.z; aw += w0 * v0.w;
    }
    float wi = g_norm_in[w];
    float4 r; r.x = ax * wi; r.y = ay * wi; r.z = az * wi; r.w = aw * wi;
    ((float4*)out)[(size_t)w * 32 + lane] = r;
}

// ---------------- tensor-core GEMM (3xTF32): C = A[n,128] @ W[128,128] + b --
// optional relu, optional per-row scale (fold out_norm for next layer's agg).
// block 256 thr (8 warps: 4 in M x 2 in N), tile 128x128, K chunked by 32.
__device__ __forceinline__ void tf32split(float v, uint32_t& hi, uint32_t& lo) {
    uint32_t h;
    asm("cvt.rna.tf32.f32 %0, %1;" : "=r"(h) : "f"(v));
    float r = v - __uint_as_float(h);
    uint32_t l;
    asm("cvt.rna.tf32.f32 %0, %1;" : "=r"(l) : "f"(r));
    hi = h; lo = l;
}

__device__ __forceinline__ void mma_tf32(float* c, const uint32_t* a, const uint32_t* b) {
    asm volatile(
        "mma.sync.aligned.m16n8k8.row.col.f32.tf32.tf32.f32 "
        "{%0,%1,%2,%3}, {%4,%5,%6,%7}, {%8,%9}, {%0,%1,%2,%3};"
        : "+f"(c[0]), "+f"(c[1]), "+f"(c[2]), "+f"(c[3])
        : "r"(a[0]), "r"(a[1]), "r"(a[2]), "r"(a[3]), "r"(b[0]), "r"(b[1]));
}

#define KCH 32
__global__ __launch_bounds__(256) void k_gemm_mma(const float* __restrict__ A,
                                                  const float* __restrict__ W,
                                                  const float* __restrict__ bias,
                                                  const float* __restrict__ rowscale,
                                                  float* __restrict__ Cout,
                                                  int n, int relu) {
    __shared__ float sA[128][36];   // [row][k-chunk], pad for conflict-free frag loads
    __shared__ float sW[KCH][136];  // [k-chunk][n], pad 136 (mod 32 = 8)

    int tid = threadIdx.x;
    int lane = tid & 31;
    int warp = tid >> 5;
    int warpM = warp & 3;           // rows warpM*32 .. +31
    int warpN = warp >> 2;          // cols warpN*64 .. +63
    int g = lane >> 2, t = lane & 3;
    int rowBase = blockIdx.x * 128;

    float acc[2][8][4];
#pragma unroll
    for (int mt = 0; mt < 2; mt++)
#pragma unroll
        for (int nt = 0; nt < 8; nt++)
#pragma unroll
            for (int i = 0; i < 4; i++) acc[mt][nt][i] = 0.0f;

    for (int k0 = 0; k0 < 128; k0 += KCH) {
        __syncthreads();
        // load A chunk: 128 rows x 32 cols = 1024 float4
#pragma unroll
        for (int i = tid; i < 1024; i += 256) {
            int r = i >> 3, c = (i & 7) * 4;
            int gr = rowBase + r;
            float4 v = make_float4(0.f, 0.f, 0.f, 0.f);
            if (gr < n) v = *(const float4*)&A[(size_t)gr * 128 + k0 + c];
            sA[r][c + 0] = v.x; sA[r][c + 1] = v.y;
            sA[r][c + 2] = v.z; sA[r][c + 3] = v.w;
        }
        // load W chunk: 32 k-rows x 128 cols = 1024 float4
#pragma unroll
        for (int i = tid; i < 1024; i += 256) {
            int kr = i >> 5, c = (i & 31) * 4;
            float4 v = *(const float4*)&W[(size_t)(k0 + kr) * 128 + c];
            sW[kr][c + 0] = v.x; sW[kr][c + 1] = v.y;
            sW[kr][c + 2] = v.z; sW[kr][c + 3] = v.w;
        }
        __syncthreads();

#pragma unroll
        for (int kk = 0; kk < KCH; kk += 8) {
            uint32_t Ah[2][4], Al[2][4];
#pragma unroll
            for (int mt = 0; mt < 2; mt++) {
                int rb = warpM * 32 + mt * 16;
                tf32split(sA[rb + g][kk + t],         Ah[mt][0], Al[mt][0]);
                tf32split(sA[rb + g + 8][kk + t],     Ah[mt][1], Al[mt][1]);
                tf32split(sA[rb + g][kk + t + 4],     Ah[mt][2], Al[mt][2]);
                tf32split(sA[rb + g + 8][kk + t + 4], Ah[mt][3], Al[mt][3]);
            }
            uint32_t Bh[8][2], Bl[8][2];
#pragma unroll
            for (int nt = 0; nt < 8; nt++) {
                int nb = warpN * 64 + nt * 8;
                tf32split(sW[kk + t][nb + g],     Bh[nt][0], Bl[nt][0]);
                tf32split(sW[kk + t + 4][nb + g], Bh[nt][1], Bl[nt][1]);
            }
#pragma unroll
            for (int mt = 0; mt < 2; mt++)
#pragma unroll
                for (int nt = 0; nt < 8; nt++) {
                    mma_tf32(acc[mt][nt], Ah[mt], Bh[nt]);
                    mma_tf32(acc[mt][nt], Ah[mt], Bl[nt]);
                    mma_tf32(acc[mt][nt], Al[mt], Bh[nt]);
                }
        }
    }

    // epilogue: bias, relu, optional rowscale, store float2 pairs
#pragma unroll
    for (int mt = 0; mt < 2; mt++) {
        int r0 = rowBase + warpM * 32 + mt * 16 + g;
        int r1 = r0 + 8;
        float rs0 = 1.0f, rs1 = 1.0f;
        if (rowscale) {
            if (r0 < n) rs0 = rowscale[r0];
            if (r1 < n) rs1 = rowscale[r1];
        }
#pragma unroll
        for (int nt = 0; nt < 8; nt++) {
            int col = warpN * 64 + nt * 8 + 2 * t;
            float b0 = bias[col], b1 = bias[col + 1];
            float v0 = acc[mt][nt][0] + b0;
            float v1 = acc[mt][nt][1] + b1;
            float v2 = acc[mt][nt][2] + b0;
            float v3 = acc[mt][nt][3] + b1;
            if (relu) {
                v0 = fmaxf(v0, 0.f); v1 = fmaxf(v1, 0.f);
                v2 = fmaxf(v2, 0.f); v3 = fmaxf(v3, 0.f);
            }
            v0 *= rs0; v1 *= rs0; v2 *= rs1; v3 *= rs1;
            if (r0 < n) *(float2*)&Cout[(size_t)r0 * 128 + col] = make_float2(v0, v1);
            if (r1 < n) *(float2*)&Cout[(size_t)r1 * 128 + col] = make_float2(v2, v3);
        }
    }
}

// ---------------- per-graph mean pooling (graph_ids sorted) -----------------
#define NPB 256
__global__ void k_pool(const float* __restrict__ x,
                       const int* __restrict__ gids, int n) {
    int f = threadIdx.x;          // feature 0..127
    int start = blockIdx.x * NPB;
    int end = min(start + NPB, n);
    if (start >= n) return;
    float sum = 0.0f;
    int cur = gids[start];
    int cnt = 0;
    for (int nd = start; nd < end; nd++) {
        int gid = gids[nd];
        if (gid != cur) {
            atomicAdd(&g_hg[cur * DF + f], sum);
            if (f == 0) atomicAdd(&g_cnt[cur], (float)cnt);
            sum = 0.0f; cnt = 0; cur = gid;
        }
        sum += x[(size_t)nd * DF + f];
        cnt++;
    }
    atomicAdd(&g_hg[cur * DF + f], sum);
    if (f == 0) atomicAdd(&g_cnt[cur], (float)cnt);
}

// ---------------- final classifier: [G, 128+64] @ Wc + bc -------------------
__global__ void k_final(const float* __restrict__ perm,
                        const float* __restrict__ Wc,
                        const float* __restrict__ bc,
                        float* __restrict__ out) {
    int g = blockIdx.x;
    int c = threadIdx.x;
    if (c >= NC) return;
    float inv = 1.0f / fmaxf(g_cnt[g], 1.0f);
    float acc = bc[c];
#pragma unroll 4
    for (int j = 0; j < DF; j++)
        acc += g_hg[g * DF + j] * inv * Wc[j * NC + c];
#pragma unroll 4
    for (int j = 0; j < NP; j++)
        acc += perm[g * NP + j] * Wc[(DF + j) * NC + c];
    out[g * NC + c] = acc;
}

// ---------------- launch ----------------------------------------------------
extern "C" void kernel_launch(void* const* d_in, const int* in_sizes, int n_in,
                              void* d_out, int out_size) {
    const float* h    = (const float*)d_in[0];
    const float* perm = (const float*)d_in[1];
    const float* W1   = (const float*)d_in[2];
    const float* b1   = (const float*)d_in[3];
    const float* W2   = (const float*)d_in[4];
    const float* b2   = (const float*)d_in[5];
    const float* Wc   = (const float*)d_in[6];
    const float* bc   = (const float*)d_in[7];
    const int* src  = (const int*)d_in[8];
    const int* dst  = (const int*)d_in[9];
    const int* gids = (const int*)d_in[10];

    int n = in_sizes[0] / DF;   // 100000
    int e = in_sizes[8];        // 1600000
    float* out = (float*)d_out;

    float *bufA, *bufB, *normOut;
    cudaGetSymbolAddress((void**)&bufA, g_bufA);
    cudaGetSymbolAddress((void**)&bufB, g_bufB);
    cudaGetSymbolAddress((void**)&normOut, g_norm_out);

    int nb = (n + 1023) / 1024;
    int gemmBlocks = (n + 127) / 128;

    k_zero<<<256, 256>>>(n);
    k_deg<<<(e + 255) / 256, 256>>>(src, dst, e);
    k_norms<<<(n + 255) / 256, 256>>>(n);
    k_scan1<<<nb, 1024>>>(n);
    k_scan2<<<1, 32>>>(nb);
    k_scan3<<<nb, 1024>>>(n, e);
    k_fill<<<(e + 255) / 256, 256>>>(src, dst, e);

    // layer 1: agg(h) -> bufA ; gemm(bufA, W1)+relu, prescaled by out_norm -> bufB
    k_agg<1><<<(n * 32 + 255) / 256, 256>>>(h, bufA, n);
    k_gemm_mma<<<gemmBlocks, 256>>>(bufA, W1, b1, normOut, bufB, n, 1);

    // layer 2: agg(bufB, already out_norm-scaled) -> bufA ; gemm(bufA, W2) -> bufB
    k_agg<0><<<(n * 32 + 255) / 256, 256>>>(bufB, bufA, n);
    k_gemm_mma<<<gemmBlocks, 256>>>(bufA, W2, b2, (const float*)nullptr, bufB, n, 0);

    // pooling + classifier
    k_pool<<<(n + NPB - 1) / NPB, 128>>>(bufB, gids, n);
    k_final<<<NG, 32>>>(perm, Wc, bc, out);
}

// round 5
// speedup vs baseline: 1.2797x; 1.0444x over previous
#include <cuda_runtime.h>
#include <cuda_fp16.h>
#include <math.h>
#include <stdint.h>

#define NMAX 100000
#define EMAX 1600000
#define DF   128
#define NG   128
#define NP   64
#define NC   10

// ---------------- scratch (static device globals; no allocs allowed) --------
__device__ __align__(16) int    g_deg_out[NMAX];
__device__ __align__(16) int    g_deg_in[NMAX];
__device__ __align__(16) float  g_norm_out[NMAX];
__device__ __align__(16) float  g_norm_in[NMAX];
__device__ __align__(16) int    g_off[NMAX + 1];
__device__ __align__(16) int    g_cursor[NMAX];
__device__ __align__(16) int    g_csr_src[EMAX];
__device__ __align__(16) float  g_bufA[(size_t)NMAX * DF];
__device__ __align__(16) float  g_bufB[(size_t)NMAX * DF];
__device__ __align__(16) __half g_bufH[(size_t)NMAX * DF];
__device__ __align__(16) float  g_hg[NG * DF];
__device__ __align__(16) float  g_cnt[NG];
__device__ __align__(16) int    g_bsum[128];

// ---------------- init ------------------------------------------------------
__global__ void k_zero(int n) {
    int i = blockIdx.x * blockDim.x + threadIdx.x;
    int stride = gridDim.x * blockDim.x;
    for (int j = i; j < n; j += stride) { g_deg_out[j] = 0; g_deg_in[j] = 0; }
    for (int j = i; j < NG * DF; j += stride) g_hg[j] = 0.0f;
    for (int j = i; j < NG; j += stride) g_cnt[j] = 0.0f;
}

__global__ void k_deg(const int* __restrict__ src,
                      const int* __restrict__ dst, int e) {
    int i = blockIdx.x * blockDim.x + threadIdx.x;
    if (i < e) {
        atomicAdd(&g_deg_out[src[i]], 1);
        atomicAdd(&g_deg_in[dst[i]], 1);
    }
}

__global__ void k_norms(int n) {
    int i = blockIdx.x * blockDim.x + threadIdx.x;
    if (i < n) {
        g_norm_out[i] = rsqrtf(fmaxf((float)g_deg_out[i], 1.0f));
        g_norm_in[i]  = rsqrtf(fmaxf((float)g_deg_in[i],  1.0f));
    }
}

// ---------------- prefix sum of in-degrees -> CSR offsets -------------------
__global__ void k_scan1(int n) {
    __shared__ int sh[1024];
    int t = threadIdx.x;
    int idx = blockIdx.x * 1024 + t;
    sh[t] = (idx < n) ? g_deg_in[idx] : 0;
    __syncthreads();
    for (int s = 512; s > 0; s >>= 1) {
        if (t < s) sh[t] += sh[t + s];
        __syncthreads();
    }
    if (t == 0) g_bsum[blockIdx.x] = sh[0];
}

__global__ void k_scan2(int nb) {
    if (threadIdx.x == 0 && blockIdx.x == 0) {
        int run = 0;
        for (int i = 0; i < nb; i++) { int v = g_bsum[i]; g_bsum[i] = run; run += v; }
    }
}

__global__ void k_scan3(int n, int e) {
    __shared__ int sh[1024];
    int t = threadIdx.x;
    int idx = blockIdx.x * 1024 + t;
    int v = (idx < n) ? g_deg_in[idx] : 0;
    sh[t] = v;
    __syncthreads();
    for (int s = 1; s < 1024; s <<= 1) {
        int x = (t >= s) ? sh[t - s] : 0;
        __syncthreads();
        sh[t] += x;
        __syncthreads();
    }
    int excl = sh[t] - v;
    if (idx < n) {
        int o = g_bsum[blockIdx.x] + excl;
        g_off[idx] = o;
        g_cursor[idx] = o;
    }
    if (blockIdx.x == 0 && t == 0) g_off[n] = e;
}

__global__ void k_fill(const int* __restrict__ src,
                       const int* __restrict__ dst, int e) {
    int i = blockIdx.x * blockDim.x + threadIdx.x;
    if (i < e) {
        int d = dst[i];
        int p = atomicAdd(&g_cursor[d], 1);
        g_csr_src[p] = src[i];
    }
}

// ---------------- convert h * out_norm -> fp16 ------------------------------
__global__ void k_h2half(const float* __restrict__ h, int n) {
    int j = blockIdx.x * blockDim.x + threadIdx.x;   // one float4 -> 4 halves
    int total = n * 32;
    if (j < total) {
        int node = j >> 5;
        float s = g_norm_out[node];
        float4 v = ((const float4*)h)[j];
        __half2 h0 = __floats2half2_rn(v.x * s, v.y * s);
        __half2 h1 = __floats2half2_rn(v.z * s, v.w * s);
        uint2 o;
        o.x = *(uint32_t*)&h0;
        o.y = *(uint32_t*)&h1;
        ((uint2*)g_bufH)[j] = o;
    }
}

// ---------------- aggregation (fp16 gather): one warp per dst node ----------
// xh already carries out_norm; out[d] = in_norm[d] * sum_e xh[src_e]
__device__ __forceinline__ void acc_h(uint2 v, float& ax, float& ay, float& az, float& aw) {
    __half2 p0 = *(__half2*)&v.x;
    __half2 p1 = *(__half2*)&v.y;
    float2 f0 = __half22float2(p0);
    float2 f1 = __half22float2(p1);
    ax += f0.x; ay += f0.y; az += f1.x; aw += f1.y;
}

__global__ void k_agg_h(const __half* __restrict__ xh, float* __restrict__ out, int n) {
    int w = (blockIdx.x * blockDim.x + threadIdx.x) >> 5;
    int lane = threadIdx.x & 31;
    if (w >= n) return;
    int beg = g_off[w], end = g_off[w + 1];
    const uint2* __restrict__ x2 = (const uint2*)xh;   // 4 halves per uint2, 32 per row
    float ax = 0.f, ay = 0.f, az = 0.f, aw = 0.f;
    int e = beg;
    for (; e + 3 < end; e += 4) {
        int s0 = g_csr_src[e];
        int s1 = g_csr_src[e + 1];
        int s2 = g_csr_src[e + 2];
        int s3 = g_csr_src[e + 3];
        uint2 v0 = x2[(size_t)s0 * 32 + lane];
        uint2 v1 = x2[(size_t)s1 * 32 + lane];
        uint2 v2 = x2[(size_t)s2 * 32 + lane];
        uint2 v3 = x2[(size_t)s3 * 32 + lane];
        acc_h(v0, ax, ay, az, aw);
        acc_h(v1, ax, ay, az, aw);
        acc_h(v2, ax, ay, az, aw);
        acc_h(v3, ax, ay, az, aw);
    }
    for (; e < end; e++) {
        int s0 = g_csr_src[e];
        uint2 v0 = x2[(size_t)s0 * 32 + lane];
        acc_h(v0, ax, ay, az, aw);
    }
    float wi = g_norm_in[w];
    float4 r; r.x = ax * wi; r.y = ay * wi; r.z = az * wi; r.w = aw * wi;
    // out row: lane holds features lane*4 .. lane*4+3
    ((float4*)out)[(size_t)w * 32 + lane] = r;
}

// ---------------- tensor-core GEMM (3xTF32): C = A[n,128] @ W[128,128] + b --
__device__ __forceinline__ void tf32split(float v, uint32_t& hi, uint32_t& lo) {
    uint32_t h;
    asm("cvt.rna.tf32.f32 %0, %1;" : "=r"(h) : "f"(v));
    float r = v - __uint_as_float(h);
    uint32_t l;
    asm("cvt.rna.tf32.f32 %0, %1;" : "=r"(l) : "f"(r));
    hi = h; lo = l;
}

__device__ __forceinline__ void mma_tf32(float* c, const uint32_t* a, const uint32_t* b) {
    asm volatile(
        "mma.sync.aligned.m16n8k8.row.col.f32.tf32.tf32.f32 "
        "{%0,%1,%2,%3}, {%4,%5,%6,%7}, {%8,%9}, {%0,%1,%2,%3};"
        : "+f"(c[0]), "+f"(c[1]), "+f"(c[2]), "+f"(c[3])
        : "r"(a[0]), "r"(a[1]), "r"(a[2]), "r"(a[3]), "r"(b[0]), "r"(b[1]));
}

#define KCH 32
// OUT_HALF=1: store fp16 (rowscale folded) into CoutH; else fp32 into CoutF.
template <int OUT_HALF, int RELU>
__global__ __launch_bounds__(256) void k_gemm_mma(const float* __restrict__ A,
                                                  const float* __restrict__ W,
                                                  const float* __restrict__ bias,
                                                  const float* __restrict__ rowscale,
                                                  float* __restrict__ CoutF,
                                                  __half* __restrict__ CoutH,
                                                  int n) {
    __shared__ float sA[128][36];
    __shared__ float sW[KCH][136];

    int tid = threadIdx.x;
    int lane = tid & 31;
    int warp = tid >> 5;
    int warpM = warp & 3;
    int warpN = warp >> 2;
    int g = lane >> 2, t = lane & 3;
    int rowBase = blockIdx.x * 128;

    float acc[2][8][4];
#pragma unroll
    for (int mt = 0; mt < 2; mt++)
#pragma unroll
        for (int nt = 0; nt < 8; nt++)
#pragma unroll
            for (int i = 0; i < 4; i++) acc[mt][nt][i] = 0.0f;

    for (int k0 = 0; k0 < 128; k0 += KCH) {
        __syncthreads();
#pragma unroll
        for (int i = tid; i < 1024; i += 256) {
            int r = i >> 3, c = (i & 7) * 4;
            int gr = rowBase + r;
            float4 v = make_float4(0.f, 0.f, 0.f, 0.f);
            if (gr < n) v = *(const float4*)&A[(size_t)gr * 128 + k0 + c];
            sA[r][c + 0] = v.x; sA[r][c + 1] = v.y;
            sA[r][c + 2] = v.z; sA[r][c + 3] = v.w;
        }
#pragma unroll
        for (int i = tid; i < 1024; i += 256) {
            int kr = i >> 5, c = (i & 31) * 4;
            float4 v = *(const float4*)&W[(size_t)(k0 + kr) * 128 + c];
            sW[kr][c + 0] = v.x; sW[kr][c + 1] = v.y;
            sW[kr][c + 2] = v.z; sW[kr][c + 3] = v.w;
        }
        __syncthreads();

#pragma unroll
        for (int kk = 0; kk < KCH; kk += 8) {
            uint32_t Ah[2][4], Al[2][4];
#pragma unroll
            for (int mt = 0; mt < 2; mt++) {
                int rb = warpM * 32 + mt * 16;
                tf32split(sA[rb + g][kk + t],         Ah[mt][0], Al[mt][0]);
                tf32split(sA[rb + g + 8][kk + t],     Ah[mt][1], Al[mt][1]);
                tf32split(sA[rb + g][kk + t + 4],     Ah[mt][2], Al[mt][2]);
                tf32split(sA[rb + g + 8][kk + t + 4], Ah[mt][3], Al[mt][3]);
            }
            uint32_t Bh[8][2], Bl[8][2];
#pragma unroll
            for (int nt = 0; nt < 8; nt++) {
                int nb = warpN * 64 + nt * 8;
                tf32split(sW[kk + t][nb + g],     Bh[nt][0], Bl[nt][0]);
                tf32split(sW[kk + t + 4][nb + g], Bh[nt][1], Bl[nt][1]);
            }
#pragma unroll
            for (int mt = 0; mt < 2; mt++)
#pragma unroll
                for (int nt = 0; nt < 8; nt++) {
                    mma_tf32(acc[mt][nt], Ah[mt], Bh[nt]);
                    mma_tf32(acc[mt][nt], Ah[mt], Bl[nt]);
                    mma_tf32(acc[mt][nt], Al[mt], Bh[nt]);
                }
        }
    }

#pragma unroll
    for (int mt = 0; mt < 2; mt++) {
        int r0 = rowBase + warpM * 32 + mt * 16 + g;
        int r1 = r0 + 8;
        float rs0 = 1.0f, rs1 = 1.0f;
        if (rowscale) {
            if (r0 < n) rs0 = rowscale[r0];
            if (r1 < n) rs1 = rowscale[r1];
        }
#pragma unroll
        for (int nt = 0; nt < 8; nt++) {
            int col = warpN * 64 + nt * 8 + 2 * t;
            float b0 = bias[col], b1 = bias[col + 1];
            float v0 = acc[mt][nt][0] + b0;
            float v1 = acc[mt][nt][1] + b1;
            float v2 = acc[mt][nt][2] + b0;
            float v3 = acc[mt][nt][3] + b1;
            if (RELU) {
                v0 = fmaxf(v0, 0.f); v1 = fmaxf(v1, 0.f);
                v2 = fmaxf(v2, 0.f); v3 = fmaxf(v3, 0.f);
            }
            v0 *= rs0; v1 *= rs0; v2 *= rs1; v3 *= rs1;
            if (OUT_HALF) {
                __half2 p0 = __floats2half2_rn(v0, v1);
                __half2 p1 = __floats2half2_rn(v2, v3);
                if (r0 < n) *(__half2*)&CoutH[(size_t)r0 * 128 + col] = p0;
                if (r1 < n) *(__half2*)&CoutH[(size_t)r1 * 128 + col] = p1;
            } else {
                if (r0 < n) *(float2*)&CoutF[(size_t)r0 * 128 + col] = make_float2(v0, v1);
                if (r1 < n) *(float2*)&CoutF[(size_t)r1 * 128 + col] = make_float2(v2, v3);
            }
        }
    }
}

// ---------------- per-graph mean pooling (graph_ids sorted) -----------------
#define NPB 256
__global__ void k_pool(const float* __restrict__ x,
                       const int* __restrict__ gids, int n) {
    int f = threadIdx.x;
    int start = blockIdx.x * NPB;
    int end = min(start + NPB, n);
    if (start >= n) return;
    float sum = 0.0f;
    int cur = gids[start];
    int cnt = 0;
    for (int nd = start; nd < end; nd++) {
        int gid = gids[nd];
        if (gid != cur) {
            atomicAdd(&g_hg[cur * DF + f], sum);
            if (f == 0) atomicAdd(&g_cnt[cur], (float)cnt);
            sum = 0.0f; cnt = 0; cur = gid;
        }
        sum += x[(size_t)nd * DF + f];
        cnt++;
    }
    atomicAdd(&g_hg[cur * DF + f], sum);
    if (f == 0) atomicAdd(&g_cnt[cur], (float)cnt);
}

// ---------------- final classifier: [G, 128+64] @ Wc + bc -------------------
__global__ void k_final(const float* __restrict__ perm,
                        const float* __restrict__ Wc,
                        const float* __restrict__ bc,
                        float* __restrict__ out) {
    int g = blockIdx.x;
    int c = threadIdx.x;
    if (c >= NC) return;
    float inv = 1.0f / fmaxf(g_cnt[g], 1.0f);
    float acc = bc[c];
#pragma unroll 4
    for (int j = 0; j < DF; j++)
        acc += g_hg[g * DF + j] * inv * Wc[j * NC + c];
#pragma unroll 4
    for (int j = 0; j < NP; j++)
        acc += perm[g * NP + j] * Wc[(DF + j) * NC + c];
    out[g * NC + c] = acc;
}

// ---------------- launch ----------------------------------------------------
extern "C" void kernel_launch(void* const* d_in, const int* in_sizes, int n_in,
                              void* d_out, int out_size) {
    const float* h    = (const float*)d_in[0];
    const float* perm = (const float*)d_in[1];
    const float* W1   = (const float*)d_in[2];
    const float* b1   = (const float*)d_in[3];
    const float* W2   = (const float*)d_in[4];
    const float* b2   = (const float*)d_in[5];
    const float* Wc   = (const float*)d_in[6];
    const float* bc   = (const float*)d_in[7];
    const int* src  = (const int*)d_in[8];
    const int* dst  = (const int*)d_in[9];
    const int* gids = (const int*)d_in[10];

    int n = in_sizes[0] / DF;   // 100000
    int e = in_sizes[8];        // 1600000
    float* out = (float*)d_out;

    float *bufA, *bufB, *normOut;
    __half* bufH;
    cudaGetSymbolAddress((void**)&bufA, g_bufA);
    cudaGetSymbolAddress((void**)&bufB, g_bufB);
    cudaGetSymbolAddress((void**)&bufH, g_bufH);
    cudaGetSymbolAddress((void**)&normOut, g_norm_out);

    int nb = (n + 1023) / 1024;
    int gemmBlocks = (n + 127) / 128;

    k_zero<<<256, 256>>>(n);
    k_deg<<<(e + 255) / 256, 256>>>(src, dst, e);
    k_norms<<<(n + 255) / 256, 256>>>(n);
    k_scan1<<<nb, 1024>>>(n);
    k_scan2<<<1, 32>>>(nb);
    k_scan3<<<nb, 1024>>>(n, e);
    k_fill<<<(e + 255) / 256, 256>>>(src, dst, e);

    // layer 1: h*out_norm -> fp16 ; agg(fp16) -> bufA ;
    //          gemm(bufA, W1)+relu, *out_norm, -> fp16 bufH
    k_h2half<<<(n * 32 + 255) / 256, 256>>>(h, n);
    k_agg_h<<<(n * 32 + 255) / 256, 256>>>(bufH, bufA, n);
    k_gemm_mma<1, 1><<<gemmBlocks, 256>>>(bufA, W1, b1, normOut, nullptr, bufH, n);

    // layer 2: agg(fp16 bufH) -> bufA ; gemm(bufA, W2) -> fp32 bufB
    k_agg_h<<<(n * 32 + 255) / 256, 256>>>(bufH, bufA, n);
    k_gemm_mma<0, 0><<<gemmBlocks, 256>>>(bufA, W2, b2, nullptr, bufB, nullptr, n);

    // pooling + classifier
    k_pool<<<(n + NPB - 1) / NPB, 128>>>(bufB, gids, n);
    k_final<<<NG, 32>>>(perm, Wc, bc, out);
}

// round 6
// speedup vs baseline: 1.9053x; 1.4889x over previous
#include <cuda_runtime.h>
#include <cuda_fp16.h>
#include <math.h>
#include <stdint.h>

#define NMAX 100000
#define EMAX 1600000
#define DF   128
#define NG   128
#define NP   64
#define NC   10

// ---------------- scratch (static device globals; no allocs allowed) --------
__device__ __align__(16) int    g_deg_out[NMAX];
__device__ __align__(16) int    g_deg_in[NMAX];
__device__ __align__(16) float  g_norm_out[NMAX];
__device__ __align__(16) float  g_norm_in[NMAX];
__device__ __align__(16) int    g_off[NMAX + 1];
__device__ __align__(16) int    g_cursor[NMAX];
__device__ __align__(16) int    g_csr_src[EMAX];
__device__ __align__(16) __half g_bufH[(size_t)NMAX * DF];   // features (fp16)
__device__ __align__(16) __half g_bufHA[(size_t)NMAX * DF];  // agg out / GEMM A (fp16)
__device__ __align__(16) float  g_bufB[(size_t)NMAX * DF];   // GEMM2 out (fp32)
__device__ __align__(16) __half g_W1t[DF * DF];              // W1^T fp16
__device__ __align__(16) __half g_W2t[DF * DF];              // W2^T fp16
__device__ __align__(16) float  g_hg[NG * DF];
__device__ __align__(16) float  g_cnt[NG];
__device__ __align__(16) int    g_bsum[128];

// ---------------- init ------------------------------------------------------
__global__ void k_zero(int n) {
    int i = blockIdx.x * blockDim.x + threadIdx.x;
    int stride = gridDim.x * blockDim.x;
    for (int j = i; j < n; j += stride) { g_deg_out[j] = 0; g_deg_in[j] = 0; }
    for (int j = i; j < NG * DF; j += stride) g_hg[j] = 0.0f;
    for (int j = i; j < NG; j += stride) g_cnt[j] = 0.0f;
}

__global__ void k_deg(const int* __restrict__ src,
                      const int* __restrict__ dst, int e) {
    int i = blockIdx.x * blockDim.x + threadIdx.x;
    if (i < e) {
        atomicAdd(&g_deg_out[src[i]], 1);
        atomicAdd(&g_deg_in[dst[i]], 1);
    }
}

__global__ void k_norms(int n) {
    int i = blockIdx.x * blockDim.x + threadIdx.x;
    if (i < n) {
        g_norm_out[i] = rsqrtf(fmaxf((float)g_deg_out[i], 1.0f));
        g_norm_in[i]  = rsqrtf(fmaxf((float)g_deg_in[i],  1.0f));
    }
}

// ---------------- prefix sum of in-degrees -> CSR offsets -------------------
__global__ void k_scan1(int n) {
    __shared__ int sh[1024];
    int t = threadIdx.x;
    int idx = blockIdx.x * 1024 + t;
    sh[t] = (idx < n) ? g_deg_in[idx] : 0;
    __syncthreads();
    for (int s = 512; s > 0; s >>= 1) {
        if (t < s) sh[t] += sh[t + s];
        __syncthreads();
    }
    if (t == 0) g_bsum[blockIdx.x] = sh[0];
}

__global__ void k_scan2(int nb) {
    if (threadIdx.x == 0 && blockIdx.x == 0) {
        int run = 0;
        for (int i = 0; i < nb; i++) { int v = g_bsum[i]; g_bsum[i] = run; run += v; }
    }
}

__global__ void k_scan3(int n, int e) {
    __shared__ int sh[1024];
    int t = threadIdx.x;
    int idx = blockIdx.x * 1024 + t;
    int v = (idx < n) ? g_deg_in[idx] : 0;
    sh[t] = v;
    __syncthreads();
    for (int s = 1; s < 1024; s <<= 1) {
        int x = (t >= s) ? sh[t - s] : 0;
        __syncthreads();
        sh[t] += x;
        __syncthreads();
    }
    int excl = sh[t] - v;
    if (idx < n) {
        int o = g_bsum[blockIdx.x] + excl;
        g_off[idx] = o;
        g_cursor[idx] = o;
    }
    if (blockIdx.x == 0 && t == 0) g_off[n] = e;
}

__global__ void k_fill(const int* __restrict__ src,
                       const int* __restrict__ dst, int e) {
    int i = blockIdx.x * blockDim.x + threadIdx.x;
    if (i < e) {
        int d = dst[i];
        int p = atomicAdd(&g_cursor[d], 1);
        g_csr_src[p] = src[i];
    }
}

// ---------------- convert h * out_norm -> fp16 ------------------------------
__global__ void k_h2half(const float* __restrict__ h, int n) {
    int j = blockIdx.x * blockDim.x + threadIdx.x;   // one float4 -> 4 halves
    int total = n * 32;
    if (j < total) {
        int node = j >> 5;
        float s = g_norm_out[node];
        float4 v = ((const float4*)h)[j];
        __half2 h0 = __floats2half2_rn(v.x * s, v.y * s);
        __half2 h1 = __floats2half2_rn(v.z * s, v.w * s);
        uint2 o;
        o.x = *(uint32_t*)&h0;
        o.y = *(uint32_t*)&h1;
        ((uint2*)g_bufH)[j] = o;
    }
}

// ---------------- W1, W2 -> fp16 transposed ---------------------------------
__global__ void k_w2half(const float* __restrict__ W1, const float* __restrict__ W2) {
    int i = blockIdx.x * blockDim.x + threadIdx.x;   // [0, 2*16384)
    if (i < DF * DF) {
        int nn = i >> 7, k = i & 127;
        g_W1t[nn * DF + k] = __float2half_rn(W1[k * DF + nn]);
    } else if (i < 2 * DF * DF) {
        int j = i - DF * DF;
        int nn = j >> 7, k = j & 127;
        g_W2t[nn * DF + k] = __float2half_rn(W2[k * DF + nn]);
    }
}

// ---------------- aggregation: one warp per dst node, 16 lanes/edge ---------
// xh carries out_norm; out[d] = fp16( in_norm[d] * sum_e xh[src_e] )
__global__ void k_agg_h(const __half* __restrict__ xh, __half* __restrict__ out, int n) {
    int w = (blockIdx.x * blockDim.x + threadIdx.x) >> 5;
    int lane = threadIdx.x & 31;
    if (w >= n) return;
    int beg = g_off[w], end = g_off[w + 1];
    int hs = lane >> 4;          // 0: even edge, 1: odd edge
    int fl = lane & 15;          // feature quad: halves fl*8..fl*8+7
    const uint4* __restrict__ x4 = (const uint4*)xh;   // 16 uint4 per row

    __half2 a0 = __float2half2_rn(0.f), a1 = a0, a2 = a0, a3 = a0;

    int e = beg;
    for (; e + 3 < end; e += 4) {
        int s0 = g_csr_src[e + hs];
        int s1 = g_csr_src[e + 2 + hs];
        uint4 v0 = x4[(size_t)s0 * 16 + fl];
        uint4 v1 = x4[(size_t)s1 * 16 + fl];
        a0 = __hadd2(a0, *(__half2*)&v0.x); a1 = __hadd2(a1, *(__half2*)&v0.y);
        a2 = __hadd2(a2, *(__half2*)&v0.z); a3 = __hadd2(a3, *(__half2*)&v0.w);
        a0 = __hadd2(a0, *(__half2*)&v1.x); a1 = __hadd2(a1, *(__half2*)&v1.y);
        a2 = __hadd2(a2, *(__half2*)&v1.z); a3 = __hadd2(a3, *(__half2*)&v1.w);
    }
    if (e + 1 < end) {
        int s0 = g_csr_src[e + hs];
        uint4 v0 = x4[(size_t)s0 * 16 + fl];
        a0 = __hadd2(a0, *(__half2*)&v0.x); a1 = __hadd2(a1, *(__half2*)&v0.y);
        a2 = __hadd2(a2, *(__half2*)&v0.z); a3 = __hadd2(a3, *(__half2*)&v0.w);
        e += 2;
    }
    if (e < end && hs == 0) {     // odd single edge: only low half-warp
        int s0 = g_csr_src[e];
        uint4 v0 = x4[(size_t)s0 * 16 + fl];
        a0 = __hadd2(a0, *(__half2*)&v0.x); a1 = __hadd2(a1, *(__half2*)&v0.y);
        a2 = __hadd2(a2, *(__half2*)&v0.z); a3 = __hadd2(a3, *(__half2*)&v0.w);
    }

    // combine the two half-warps (feature-aligned partners differ by lane bit 4)
    uint32_t b;
    b = __shfl_xor_sync(0xffffffffu, *(uint32_t*)&a0, 16); a0 = __hadd2(a0, *(__half2*)&b);
    b = __shfl_xor_sync(0xffffffffu, *(uint32_t*)&a1, 16); a1 = __hadd2(a1, *(__half2*)&b);
    b = __shfl_xor_sync(0xffffffffu, *(uint32_t*)&a2, 16); a2 = __hadd2(a2, *(__half2*)&b);
    b = __shfl_xor_sync(0xffffffffu, *(uint32_t*)&a3, 16); a3 = __hadd2(a3, *(__half2*)&b);

    if (lane < 16) {
        float wi = g_norm_in[w];
        float2 f0 = __half22float2(a0), f1 = __half22float2(a1);
        float2 f2 = __half22float2(a2), f3 = __half22float2(a3);
        __half2 o0 = __floats2half2_rn(f0.x * wi, f0.y * wi);
        __half2 o1 = __floats2half2_rn(f1.x * wi, f1.y * wi);
        __half2 o2 = __floats2half2_rn(f2.x * wi, f2.y * wi);
        __half2 o3 = __floats2half2_rn(f3.x * wi, f3.y * wi);
        uint4 o;
        o.x = *(uint32_t*)&o0; o.y = *(uint32_t*)&o1;
        o.z = *(uint32_t*)&o2; o.w = *(uint32_t*)&o3;
        ((uint4*)out)[(size_t)w * 16 + fl] = o;
    }
}

// ---------------- fp16 tensor-core GEMM: C = A[n,128] @ W[128,128] + b ------
// A fp16 row-major, Wt fp16 [n][k] (transposed). fp32 accumulate.
// block 256 thr (8 warps: 4 in M x 2 in N), tile 128x128, K chunked by 64.
__device__ __forceinline__ void mma_f16(float* c, const uint32_t* a, const uint32_t* b) {
    asm volatile(
        "mma.sync.aligned.m16n8k16.row.col.f32.f16.f16.f32 "
        "{%0,%1,%2,%3}, {%4,%5,%6,%7}, {%8,%9}, {%0,%1,%2,%3};"
        : "+f"(c[0]), "+f"(c[1]), "+f"(c[2]), "+f"(c[3])
        : "r"(a[0]), "r"(a[1]), "r"(a[2]), "r"(a[3]), "r"(b[0]), "r"(b[1]));
}

#define KCH 64
template <int OUT_HALF, int RELU>
__global__ __launch_bounds__(256) void k_gemm_h(const __half* __restrict__ A,
                                                const __half* __restrict__ Wt,
                                                const float* __restrict__ bias,
                                                const float* __restrict__ rowscale,
                                                float* __restrict__ CoutF,
                                                __half* __restrict__ CoutH,
                                                int n) {
    __shared__ __half sA[128][72];   // pad 72 halves (36 words; 4g+t conflict-free)
    __shared__ __half sB[128][72];   // Wt rows: [n][k-chunk]

    int tid = threadIdx.x;
    int lane = tid & 31;
    int warp = tid >> 5;
    int warpM = warp & 3;            // rows warpM*32 .. +31
    int warpN = warp >> 2;           // cols warpN*64 .. +63
    int g = lane >> 2, t = lane & 3;
    int rowBase = blockIdx.x * 128;

    float acc[2][8][4];
#pragma unroll
    for (int mt = 0; mt < 2; mt++)
#pragma unroll
        for (int nt = 0; nt < 8; nt++)
#pragma unroll
            for (int i = 0; i < 4; i++) acc[mt][nt][i] = 0.0f;

    for (int k0 = 0; k0 < 128; k0 += KCH) {
        __syncthreads();
        // A chunk: 128 rows x 64 halves = 1024 uint4
#pragma unroll
        for (int i = tid; i < 1024; i += 256) {
            int r = i >> 3, c = (i & 7) * 8;
            int gr = rowBase + r;
            uint4 v = make_uint4(0u, 0u, 0u, 0u);
            if (gr < n) v = *(const uint4*)&A[(size_t)gr * 128 + k0 + c];
            *(uint4*)&sA[r][c] = v;
        }
        // W chunk: 128 n-rows x 64 k = 1024 uint4
#pragma unroll
        for (int i = tid; i < 1024; i += 256) {
            int r = i >> 3, c = (i & 7) * 8;
            uint4 v = *(const uint4*)&Wt[(size_t)r * 128 + k0 + c];
            *(uint4*)&sB[r][c] = v;
        }
        __syncthreads();

#pragma unroll
        for (int kk = 0; kk < KCH; kk += 16) {
            uint32_t Af[2][4];
#pragma unroll
            for (int mt = 0; mt < 2; mt++) {
                int rb = warpM * 32 + mt * 16;
                Af[mt][0] = *(const uint32_t*)&sA[rb + g][kk + 2 * t];
                Af[mt][1] = *(const uint32_t*)&sA[rb + g + 8][kk + 2 * t];
                Af[mt][2] = *(const uint32_t*)&sA[rb + g][kk + 8 + 2 * t];
                Af[mt][3] = *(const uint32_t*)&sA[rb + g + 8][kk + 8 + 2 * t];
            }
            uint32_t Bf[8][2];
#pragma unroll
            for (int nt = 0; nt < 8; nt++) {
                int nb = warpN * 64 + nt * 8;
                Bf[nt][0] = *(const uint32_t*)&sB[nb + g][kk + 2 * t];
                Bf[nt][1] = *(const uint32_t*)&sB[nb + g][kk + 8 + 2 * t];
            }
#pragma unroll
            for (int mt = 0; mt < 2; mt++)
#pragma unroll
                for (int nt = 0; nt < 8; nt++)
                    mma_f16(acc[mt][nt], Af[mt], Bf[nt]);
        }
    }

    // epilogue: bias, relu, optional rowscale
#pragma unroll
    for (int mt = 0; mt < 2; mt++) {
        int r0 = rowBase + warpM * 32 + mt * 16 + g;
        int r1 = r0 + 8;
        float rs0 = 1.0f, rs1 = 1.0f;
        if (rowscale) {
            if (r0 < n) rs0 = rowscale[r0];
            if (r1 < n) rs1 = rowscale[r1];
        }
#pragma unroll
        for (int nt = 0; nt < 8; nt++) {
            int col = warpN * 64 + nt * 8 + 2 * t;
            float b0 = bias[col], b1 = bias[col + 1];
            float v0 = acc[mt][nt][0] + b0;
            float v1 = acc[mt][nt][1] + b1;
            float v2 = acc[mt][nt][2] + b0;
            float v3 = acc[mt][nt][3] + b1;
            if (RELU) {
                v0 = fmaxf(v0, 0.f); v1 = fmaxf(v1, 0.f);
                v2 = fmaxf(v2, 0.f); v3 = fmaxf(v3, 0.f);
            }
            v0 *= rs0; v1 *= rs0; v2 *= rs1; v3 *= rs1;
            if (OUT_HALF) {
                __half2 p0 = __floats2half2_rn(v0, v1);
                __half2 p1 = __floats2half2_rn(v2, v3);
                if (r0 < n) *(__half2*)&CoutH[(size_t)r0 * 128 + col] = p0;
                if (r1 < n) *(__half2*)&CoutH[(size_t)r1 * 128 + col] = p1;
            } else {
                if (r0 < n) *(float2*)&CoutF[(size_t)r0 * 128 + col] = make_float2(v0, v1);
                if (r1 < n) *(float2*)&CoutF[(size_t)r1 * 128 + col] = make_float2(v2, v3);
            }
        }
    }
}

// ---------------- per-graph mean pooling (graph_ids sorted) -----------------
#define NPB 256
__global__ void k_pool(const float* __restrict__ x,
                       const int* __restrict__ gids, int n) {
    int f = threadIdx.x;
    int start = blockIdx.x * NPB;
    int end = min(start + NPB, n);
    if (start >= n) return;
    float sum = 0.0f;
    int cur = gids[start];
    int cnt = 0;
    for (int nd = start; nd < end; nd++) {
        int gid = gids[nd];
        if (gid != cur) {
            atomicAdd(&g_hg[cur * DF + f], sum);
            if (f == 0) atomicAdd(&g_cnt[cur], (float)cnt);
            sum = 0.0f; cnt = 0; cur = gid;
        }
        sum += x[(size_t)nd * DF + f];
        cnt++;
    }
    atomicAdd(&g_hg[cur * DF + f], sum);
    if (f == 0) atomicAdd(&g_cnt[cur], (float)cnt);
}

// ---------------- final classifier: [G, 128+64] @ Wc + bc -------------------
__global__ void k_final(const float* __restrict__ perm,
                        const float* __restrict__ Wc,
                        const float* __restrict__ bc,
                        float* __restrict__ out) {
    int g = blockIdx.x;
    int c = threadIdx.x;
    if (c >= NC) return;
    float inv = 1.0f / fmaxf(g_cnt[g], 1.0f);
    float acc = bc[c];
#pragma unroll 4
    for (int j = 0; j < DF; j++)
        acc += g_hg[g * DF + j] * inv * Wc[j * NC + c];
#pragma unroll 4
    for (int j = 0; j < NP; j++)
        acc += perm[g * NP + j] * Wc[(DF + j) * NC + c];
    out[g * NC + c] = acc;
}

// ---------------- launch ----------------------------------------------------
extern "C" void kernel_launch(void* const* d_in, const int* in_sizes, int n_in,
                              void* d_out, int out_size) {
    const float* h    = (const float*)d_in[0];
    const float* perm = (const float*)d_in[1];
    const float* W1   = (const float*)d_in[2];
    const float* b1   = (const float*)d_in[3];
    const float* W2   = (const float*)d_in[4];
    const float* b2   = (const float*)d_in[5];
    const float* Wc   = (const float*)d_in[6];
    const float* bc   = (const float*)d_in[7];
    const int* src  = (const int*)d_in[8];
    const int* dst  = (const int*)d_in[9];
    const int* gids = (const int*)d_in[10];

    int n = in_sizes[0] / DF;   // 100000
    int e = in_sizes[8];        // 1600000
    float* out = (float*)d_out;

    float *bufB, *normOut;
    __half *bufH, *bufHA, *w1t, *w2t;
    cudaGetSymbolAddress((void**)&bufB, g_bufB);
    cudaGetSymbolAddress((void**)&bufH, g_bufH);
    cudaGetSymbolAddress((void**)&bufHA, g_bufHA);
    cudaGetSymbolAddress((void**)&w1t, g_W1t);
    cudaGetSymbolAddress((void**)&w2t, g_W2t);
    cudaGetSymbolAddress((void**)&normOut, g_norm_out);

    int nb = (n + 1023) / 1024;
    int gemmBlocks = (n + 127) / 128;

    k_zero<<<256, 256>>>(n);
    k_deg<<<(e + 255) / 256, 256>>>(src, dst, e);
    k_norms<<<(n + 255) / 256, 256>>>(n);
    k_scan1<<<nb, 1024>>>(n);
    k_scan2<<<1, 32>>>(nb);
    k_scan3<<<nb, 1024>>>(n, e);
    k_fill<<<(e + 255) / 256, 256>>>(src, dst, e);

    k_h2half<<<(n * 32 + 255) / 256, 256>>>(h, n);
    k_w2half<<<(2 * DF * DF + 255) / 256, 256>>>(W1, W2);

    // layer 1: agg(bufH) -> bufHA ; gemm(bufHA, W1t)+relu, *out_norm -> bufH (fp16)
    k_agg_h<<<(n * 32 + 255) / 256, 256>>>(bufH, bufHA, n);
    k_gemm_h<1, 1><<<gemmBlocks, 256>>>(bufHA, w1t, b1, normOut, nullptr, bufH, n);

    // layer 2: agg(bufH) -> bufHA ; gemm(bufHA, W2t) -> bufB (fp32)
    k_agg_h<<<(n * 32 + 255) / 256, 256>>>(bufH, bufHA, n);
    k_gemm_h<0, 0><<<gemmBlocks, 256>>>(bufHA, w2t, b2, nullptr, bufB, nullptr, n);

    // pooling + classifier
    k_pool<<<(n + NPB - 1) / NPB, 128>>>(bufB, gids, n);
    k_final<<<NG, 32>>>(perm, Wc, bc, out);
}